// round 1
// baseline (speedup 1.0000x reference)
#include <cuda_runtime.h>
#include <cuda_bf16.h>
#include <cstdint>

// Problem constants
#define N_NODES  100000
#define E_EDGES  1600000
#define M_EDGES  (E_EDGES + N_NODES)   // with self loops = 1,700,000
#define IN_DIM   128
#define D_DIM    128
#define H_HEADS  4
#define C_CH     32

// ---------------- device scratch (no runtime allocation allowed) ----------------
__device__ float g_hin[N_NODES * D_DIM];    // residual branch
__device__ float g_xp [N_NODES * D_DIM];    // GAT projection
__device__ float g_asrc[N_NODES * H_HEADS];
__device__ float g_adst[N_NODES * H_HEADS];
__device__ int   g_cnt[N_NODES];
__device__ int   g_rowstart[N_NODES];
__device__ int   g_cursor[N_NODES];
__device__ int   g_csr[M_EDGES];
__device__ int   g_blksum[256];
__device__ int   g_blkoff[256];
__device__ float g_colsum[D_DIM];
__device__ float g_colsumsq[D_DIM];

__device__ __forceinline__ float lrelu02(float v) { return v > 0.f ? v : 0.2f * v; }

// ---------------- K0: init ----------------
__global__ void init_kernel() {
    int i = blockIdx.x * blockDim.x + threadIdx.x;
    if (i < N_NODES) g_cnt[i] = 0;
    if (i < D_DIM) { g_colsum[i] = 0.f; g_colsumsq[i] = 0.f; }
}

// ---------------- K1: fused dual GEMM (h_in and xp), packed f32x2 ----------------
// Tile: BM=64 rows, BN=256 cols (lin_w cols 0..127, gat_w cols 128..255), BK=32 chunks.
// 256 threads; thread computes 8 rows x 8 cols as 8x4 f32x2 accumulators.
__global__ __launch_bounds__(256) void gemm_kernel(
    const float* __restrict__ x, const float* __restrict__ lin_w,
    const float* __restrict__ lin_b, const float* __restrict__ gat_w)
{
    extern __shared__ float sm[];
    float* xs = sm;              // [64][128] = 32KB
    float* ws = sm + 64 * 128;   // [32][256] = 32KB

    const int tid = threadIdx.x;
    const int n0  = blockIdx.x * 64;

    // load x tile (full K)
#pragma unroll
    for (int i = 0; i < 8; i++) {
        int f = tid + i * 256;          // float4 index over 64*32
        int row = f >> 5, c4 = f & 31;
        float4 v = make_float4(0.f, 0.f, 0.f, 0.f);
        if (n0 + row < N_NODES) v = reinterpret_cast<const float4*>(x)[(n0 + row) * 32 + c4];
        reinterpret_cast<float4*>(xs)[f] = v;
    }

    unsigned long long acc[8][4];
#pragma unroll
    for (int r = 0; r < 8; r++)
#pragma unroll
        for (int p = 0; p < 4; p++) acc[r][p] = 0ull;

    const int tr = tid >> 5, tc = tid & 31;
    const int r0 = tr * 8, c0 = tc * 8;

    for (int cc = 0; cc < 4; cc++) {
        __syncthreads();
        // load W chunk [32][256]
#pragma unroll
        for (int i = 0; i < 8; i++) {
            int f = tid + i * 256;      // float4 index over 32*64
            int k = f >> 6, j4 = f & 63;
            const float* sp = (j4 < 32) ? (lin_w + (cc * 32 + k) * 128 + j4 * 4)
                                        : (gat_w + (cc * 32 + k) * 128 + (j4 - 32) * 4);
            reinterpret_cast<float4*>(ws)[f] = *reinterpret_cast<const float4*>(sp);
        }
        __syncthreads();

#pragma unroll
        for (int k4 = 0; k4 < 8; k4++) {
            float4 xv[8];
#pragma unroll
            for (int r = 0; r < 8; r++)
                xv[r] = *reinterpret_cast<const float4*>(&xs[(r0 + r) * 128 + cc * 32 + k4 * 4]);
#pragma unroll
            for (int kk = 0; kk < 4; kk++) {
                const unsigned long long* wp =
                    reinterpret_cast<const unsigned long long*>(ws + (k4 * 4 + kk) * 256 + c0);
                unsigned long long w0 = wp[0], w1 = wp[1], w2 = wp[2], w3 = wp[3];
#pragma unroll
                for (int r = 0; r < 8; r++) {
                    float xf = (kk == 0) ? xv[r].x : (kk == 1) ? xv[r].y : (kk == 2) ? xv[r].z : xv[r].w;
                    unsigned xu = __float_as_uint(xf);
                    unsigned long long xd;
                    asm("mov.b64 %0, {%1, %1};" : "=l"(xd) : "r"(xu));
                    asm("fma.rn.f32x2 %0, %1, %2, %0;" : "+l"(acc[r][0]) : "l"(xd), "l"(w0));
                    asm("fma.rn.f32x2 %0, %1, %2, %0;" : "+l"(acc[r][1]) : "l"(xd), "l"(w1));
                    asm("fma.rn.f32x2 %0, %1, %2, %0;" : "+l"(acc[r][2]) : "l"(xd), "l"(w2));
                    asm("fma.rn.f32x2 %0, %1, %2, %0;" : "+l"(acc[r][3]) : "l"(xd), "l"(w3));
                }
            }
        }
    }

    // store: a thread's 8 cols live entirely in one half (lin or gat)
#pragma unroll
    for (int r = 0; r < 8; r++) {
        int n = n0 + r0 + r;
        if (n >= N_NODES) continue;
        float o[8];
#pragma unroll
        for (int p = 0; p < 4; p++) {
            unsigned lo, hi;
            asm("mov.b64 {%0, %1}, %2;" : "=r"(lo), "=r"(hi) : "l"(acc[r][p]));
            o[2 * p] = __uint_as_float(lo);
            o[2 * p + 1] = __uint_as_float(hi);
        }
        if (c0 < 128) {
            float4 b0 = *reinterpret_cast<const float4*>(&lin_b[c0]);
            float4 b1 = *reinterpret_cast<const float4*>(&lin_b[c0 + 4]);
            float4 v0 = make_float4(o[0] + b0.x, o[1] + b0.y, o[2] + b0.z, o[3] + b0.w);
            float4 v1 = make_float4(o[4] + b1.x, o[5] + b1.y, o[6] + b1.z, o[7] + b1.w);
            *reinterpret_cast<float4*>(&g_hin[n * 128 + c0]) = v0;
            *reinterpret_cast<float4*>(&g_hin[n * 128 + c0 + 4]) = v1;
        } else {
            int j = c0 - 128;
            *reinterpret_cast<float4*>(&g_xp[n * 128 + j])     = make_float4(o[0], o[1], o[2], o[3]);
            *reinterpret_cast<float4*>(&g_xp[n * 128 + j + 4]) = make_float4(o[4], o[5], o[6], o[7]);
        }
    }
}

// ---------------- K2: per-node attention logits ----------------
__global__ void att_kernel(const float* __restrict__ att_src, const float* __restrict__ att_dst) {
    int n = blockIdx.x;
    int t = threadIdx.x;                 // 128: t = h*32 + c
    float v = g_xp[n * 128 + t];
    float s = v * att_src[t];
    float d = v * att_dst[t];
#pragma unroll
    for (int o = 16; o > 0; o >>= 1) {
        s += __shfl_xor_sync(0xffffffffu, s, o);
        d += __shfl_xor_sync(0xffffffffu, d, o);
    }
    if ((t & 31) == 0) {
        int h = t >> 5;
        g_asrc[n * 4 + h] = s;
        g_adst[n * 4 + h] = d;
    }
}

// ---------------- K3: degree histogram ----------------
__global__ void count_kernel(const int* __restrict__ ei) {
    int i = blockIdx.x * blockDim.x + threadIdx.x;
    if (i >= M_EDGES) return;
    int d = (i < E_EDGES) ? ei[E_EDGES + i] : (i - E_EDGES);
    atomicAdd(&g_cnt[d], 1);
}

// ---------------- K4-K6: exclusive scan of g_cnt -> g_rowstart ----------------
__global__ void scanA_kernel() {
    __shared__ int sh[256];
    int t = threadIdx.x;
    int base = blockIdx.x * 1024 + t * 4;
    int v0 = 0, v1 = 0, v2 = 0, v3 = 0;
    if (base + 0 < N_NODES) v0 = g_cnt[base + 0];
    if (base + 1 < N_NODES) v1 = g_cnt[base + 1];
    if (base + 2 < N_NODES) v2 = g_cnt[base + 2];
    if (base + 3 < N_NODES) v3 = g_cnt[base + 3];
    int s = v0 + v1 + v2 + v3;
    sh[t] = s; __syncthreads();
    for (int off = 1; off < 256; off <<= 1) {
        int u = (t >= off) ? sh[t - off] : 0; __syncthreads();
        sh[t] += u; __syncthreads();
    }
    int run = sh[t] - s;                 // exclusive within block
    if (base + 0 < N_NODES) g_rowstart[base + 0] = run; run += v0;
    if (base + 1 < N_NODES) g_rowstart[base + 1] = run; run += v1;
    if (base + 2 < N_NODES) g_rowstart[base + 2] = run; run += v2;
    if (base + 3 < N_NODES) g_rowstart[base + 3] = run;
    if (t == 255) g_blksum[blockIdx.x] = sh[255];
}

__global__ void scanB_kernel(int nb) {
    __shared__ int sh[256];
    int t = threadIdx.x;
    int v = (t < nb) ? g_blksum[t] : 0;
    sh[t] = v; __syncthreads();
    for (int off = 1; off < 256; off <<= 1) {
        int u = (t >= off) ? sh[t - off] : 0; __syncthreads();
        sh[t] += u; __syncthreads();
    }
    if (t < nb) g_blkoff[t] = sh[t] - v;
}

__global__ void scanC_kernel() {
    int t = threadIdx.x;
    int off = g_blkoff[blockIdx.x];
#pragma unroll
    for (int j = 0; j < 4; j++) {
        int i = blockIdx.x * 1024 + t * 4 + j;
        if (i < N_NODES) {
            int r = g_rowstart[i] + off;
            g_rowstart[i] = r;
            g_cursor[i] = r;
        }
    }
}

// ---------------- K7: scatter edges into CSR ----------------
__global__ void scatter_kernel(const int* __restrict__ ei) {
    int i = blockIdx.x * blockDim.x + threadIdx.x;
    if (i >= M_EDGES) return;
    int s, d;
    if (i < E_EDGES) { s = ei[i]; d = ei[E_EDGES + i]; }
    else             { s = d = i - E_EDGES; }
    int pos = atomicAdd(&g_cursor[d], 1);
    g_csr[pos] = s;
}

// ---------------- K8: one warp per dst node: softmax + weighted aggregation ----------------
__global__ void agg_kernel(const float* __restrict__ gat_bias, float* __restrict__ out) {
    int warp = (blockIdx.x * blockDim.x + threadIdx.x) >> 5;
    int lane = threadIdx.x & 31;
    if (warp >= N_NODES) return;
    int n = warp;
    int rs = g_rowstart[n];
    int deg = g_cnt[n];
    float4 ad = reinterpret_cast<const float4*>(g_adst)[n];

    // denominator: lane-strided over edges, all 4 heads
    float d0 = 0.f, d1 = 0.f, d2 = 0.f, d3 = 0.f;
    for (int e = rs + lane; e < rs + deg; e += 32) {
        int s = g_csr[e];
        float4 as = reinterpret_cast<const float4*>(g_asrc)[s];
        d0 += __expf(lrelu02(as.x + ad.x));
        d1 += __expf(lrelu02(as.y + ad.y));
        d2 += __expf(lrelu02(as.z + ad.z));
        d3 += __expf(lrelu02(as.w + ad.w));
    }
#pragma unroll
    for (int o = 16; o > 0; o >>= 1) {
        d0 += __shfl_xor_sync(0xffffffffu, d0, o);
        d1 += __shfl_xor_sync(0xffffffffu, d1, o);
        d2 += __shfl_xor_sync(0xffffffffu, d2, o);
        d3 += __shfl_xor_sync(0xffffffffu, d3, o);
    }
    int h = lane >> 3;                   // lane covers cols lane*4..lane*4+3, head = (lane*4)/32
    float ad_h  = (h == 0) ? ad.x : (h == 1) ? ad.y : (h == 2) ? ad.z : ad.w;
    float den_h = (h == 0) ? d0  : (h == 1) ? d1  : (h == 2) ? d2  : d3;
    float inv = 1.0f / den_h;            // >0 guaranteed by self loop

    float4 acc = make_float4(0.f, 0.f, 0.f, 0.f);
    for (int e = rs; e < rs + deg; e++) {
        int s = g_csr[e];                                    // broadcast
        float ash = g_asrc[s * 4 + h];                       // 16B/warp
        float alpha = __expf(lrelu02(ash + ad_h)) * inv;
        float4 xv = reinterpret_cast<const float4*>(g_xp)[s * 32 + lane];
        acc.x += alpha * xv.x; acc.y += alpha * xv.y;
        acc.z += alpha * xv.z; acc.w += alpha * xv.w;
    }
    float4 b = reinterpret_cast<const float4*>(gat_bias)[lane];
    acc.x += b.x; acc.y += b.y; acc.z += b.z; acc.w += b.w;
    reinterpret_cast<float4*>(out)[n * 32 + lane] = acc;     // pre-BN h
}

// ---------------- K9: column statistics for BatchNorm ----------------
__global__ void colstats_kernel(const float* __restrict__ y) {
    int t = threadIdx.x;                 // 128 cols
    float s = 0.f, ss = 0.f;
    for (int r = blockIdx.x; r < N_NODES; r += gridDim.x) {
        float v = y[r * 128 + t];
        s += v; ss += v * v;
    }
    atomicAdd(&g_colsum[t], s);
    atomicAdd(&g_colsumsq[t], ss);
}

// ---------------- K10: BN + ELU + residual ----------------
__global__ void final_kernel(float* __restrict__ out,
                             const float* __restrict__ gamma, const float* __restrict__ beta) {
    int i = blockIdx.x * blockDim.x + threadIdx.x;
    if (i >= N_NODES * 128) return;
    int c = i & 127;
    const float invN = 1.0f / (float)N_NODES;
    float mu = g_colsum[c] * invN;
    float var = g_colsumsq[c] * invN - mu * mu;
    float y = out[i];
    float t = (y - mu) * rsqrtf(var + 1e-5f) * gamma[c] + beta[c];
    float h = t > 0.f ? t : expm1f(t);
    out[i] = g_hin[i] + h;
}

// ---------------- launch ----------------
extern "C" void kernel_launch(void* const* d_in, const int* in_sizes, int n_in,
                              void* d_out, int out_size) {
    const float* x        = (const float*)d_in[0];
    const int*   ei       = (const int*)  d_in[1];
    const float* lin_w    = (const float*)d_in[2];
    const float* lin_b    = (const float*)d_in[3];
    const float* gat_w    = (const float*)d_in[4];
    const float* att_src  = (const float*)d_in[5];
    const float* att_dst  = (const float*)d_in[6];
    const float* gat_bias = (const float*)d_in[7];
    const float* bn_gamma = (const float*)d_in[8];
    const float* bn_beta  = (const float*)d_in[9];
    float* out = (float*)d_out;

    cudaFuncSetAttribute(gemm_kernel, cudaFuncAttributeMaxDynamicSharedMemorySize, 65536);

    const int NB = (N_NODES + 1023) / 1024;   // 98 scan blocks

    init_kernel<<<(N_NODES + 255) / 256, 256>>>();
    gemm_kernel<<<(N_NODES + 63) / 64, 256, 65536>>>(x, lin_w, lin_b, gat_w);
    att_kernel<<<N_NODES, 128>>>(att_src, att_dst);
    count_kernel<<<(M_EDGES + 255) / 256, 256>>>(ei);
    scanA_kernel<<<NB, 256>>>();
    scanB_kernel<<<1, 256>>>(NB);
    scanC_kernel<<<NB, 256>>>();
    scatter_kernel<<<(M_EDGES + 255) / 256, 256>>>(ei);
    agg_kernel<<<(N_NODES + 7) / 8, 256>>>(gat_bias, out);
    colstats_kernel<<<512, 128>>>(out);
    final_kernel<<<(N_NODES * 128 + 255) / 256, 256>>>(out, bn_gamma, bn_beta);
}

// round 5
// speedup vs baseline: 1.1801x; 1.1801x over previous
#include <cuda_runtime.h>
#include <cuda_bf16.h>
#include <mma.h>
#include <cstdint>

using namespace nvcuda;

// Problem constants
#define N_NODES  100000
#define E_EDGES  1600000
#define M_EDGES  (E_EDGES + N_NODES)   // 1,700,000 with self loops
#define IN_DIM   128
#define D_DIM    128
#define H_HEADS  4
#define C_CH     32

// ---------------- device scratch ----------------
__device__ float g_hin[N_NODES * D_DIM];
__device__ float g_xp [N_NODES * D_DIM];
__device__ float g_asrc[N_NODES * H_HEADS];
__device__ float g_adst[N_NODES * H_HEADS];
__device__ int   g_cnt[N_NODES];
__device__ int   g_rowstart[N_NODES];
__device__ int   g_cursor[N_NODES];
__device__ int   g_csr[M_EDGES];
__device__ int   g_blksum[256];
__device__ int   g_blkoff[256];
__device__ float g_colsum[D_DIM];
__device__ float g_colsumsq[D_DIM];

__device__ __forceinline__ float lrelu02(float v) { return v > 0.f ? v : 0.2f * v; }

// ---------------- K0: init ----------------
__global__ void init_kernel() {
    int i = blockIdx.x * blockDim.x + threadIdx.x;
    if (i < N_NODES) g_cnt[i] = 0;
    if (i < D_DIM) { g_colsum[i] = 0.f; g_colsumsq[i] = 0.f; }
}

// ---------------- K1: wmma tf32 GEMM (+ fused attention logits on gat half) ----------------
// grid = (ceil(N/128), 2): y=0 -> h_in = x@lin_w + lin_b ; y=1 -> xp = x@gat_w, + att logits.
// Block 256 thr (8 warps). BM=128, BN=128, BK=32. Warp tile 32x64 (2x4 frags of 16x16x8).
#define LDA 40    // 32 + 8 pad (floats)
#define LDB 136   // 128 + 8 pad
#define LDC_S 132 // 128 + 4 pad
#define GEMM_SMEM (128 * LDC_S * 4)   // 67584 B; load buffers (128*40 + 32*136 = 37.9KB) overlap

__global__ __launch_bounds__(256) void gemm_kernel(
    const float* __restrict__ x, const float* __restrict__ lin_w,
    const float* __restrict__ lin_b, const float* __restrict__ gat_w,
    const float* __restrict__ att_src, const float* __restrict__ att_dst)
{
    extern __shared__ float sm[];
    float* xs = sm;                  // [128][LDA]
    float* ws = sm + 128 * LDA;      // [32][LDB]
    float* cs = sm;                  // epilogue reuse [128][LDC_S]

    const bool is_gat = (blockIdx.y != 0);
    const float* W = is_gat ? gat_w : lin_w;
    const int n0 = blockIdx.x * 128;
    const int tid = threadIdx.x, wid = tid >> 5, lane = tid & 31;
    const int wr = wid & 3;          // warp row group: rows wr*32..wr*32+31
    const int wc = wid >> 2;         // warp col group: cols wc*64..wc*64+63

    wmma::fragment<wmma::accumulator, 16, 16, 8, float> acc[2][4];
#pragma unroll
    for (int i = 0; i < 2; i++)
#pragma unroll
        for (int j = 0; j < 4; j++) wmma::fill_fragment(acc[i][j], 0.0f);

    for (int kc = 0; kc < 4; kc++) {
        __syncthreads();
        // load x chunk [128 rows][32 cols] as float4
#pragma unroll
        for (int i = 0; i < 4; i++) {
            int f = tid + i * 256;              // float4 index over 128*8
            int row = f >> 3, c4 = f & 7;
            float4 v = make_float4(0.f, 0.f, 0.f, 0.f);
            if (n0 + row < N_NODES)
                v = reinterpret_cast<const float4*>(x)[(n0 + row) * 32 + kc * 8 + c4];
            *reinterpret_cast<float4*>(&xs[row * LDA + c4 * 4]) = v;
        }
        // load W chunk [32 k][128 j] as float4
#pragma unroll
        for (int i = 0; i < 4; i++) {
            int f = tid + i * 256;              // float4 index over 32*32
            int row = f >> 5, c4 = f & 31;
            *reinterpret_cast<float4*>(&ws[row * LDB + c4 * 4]) =
                reinterpret_cast<const float4*>(W)[(kc * 32 + row) * 32 + c4];
        }
        __syncthreads();

#pragma unroll
        for (int kk = 0; kk < 4; kk++) {
            wmma::fragment<wmma::matrix_a, 16, 16, 8, wmma::precision::tf32, wmma::row_major> a[2];
            wmma::fragment<wmma::matrix_b, 16, 16, 8, wmma::precision::tf32, wmma::row_major> b[4];
#pragma unroll
            for (int i = 0; i < 2; i++) {
                wmma::load_matrix_sync(a[i], &xs[(wr * 32 + i * 16) * LDA + kk * 8], LDA);
#pragma unroll
                for (int t = 0; t < a[i].num_elements; t++)
                    a[i].x[t] = wmma::__float_to_tf32(a[i].x[t]);
            }
#pragma unroll
            for (int j = 0; j < 4; j++) {
                wmma::load_matrix_sync(b[j], &ws[(kk * 8) * LDB + wc * 64 + j * 16], LDB);
#pragma unroll
                for (int t = 0; t < b[j].num_elements; t++)
                    b[j].x[t] = wmma::__float_to_tf32(b[j].x[t]);
            }
#pragma unroll
            for (int i = 0; i < 2; i++)
#pragma unroll
                for (int j = 0; j < 4; j++)
                    wmma::mma_sync(acc[i][j], a[i], b[j], acc[i][j]);
        }
    }

    __syncthreads();
#pragma unroll
    for (int i = 0; i < 2; i++)
#pragma unroll
        for (int j = 0; j < 4; j++)
            wmma::store_matrix_sync(&cs[(wr * 32 + i * 16) * LDC_S + wc * 64 + j * 16],
                                    acc[i][j], LDC_S, wmma::mem_row_major);
    __syncthreads();

    // epilogue: warp handles 16 rows; lane covers 4 cols (lane*4 .. lane*4+3)
    float4 b4 = make_float4(0.f, 0.f, 0.f, 0.f);
    float4 as4 = b4, ad4 = b4;
    if (is_gat) {
        as4 = *reinterpret_cast<const float4*>(&att_src[lane * 4]);
        ad4 = *reinterpret_cast<const float4*>(&att_dst[lane * 4]);
    } else {
        b4 = *reinterpret_cast<const float4*>(&lin_b[lane * 4]);
    }
    const int h = lane >> 3;     // head of this lane's columns
#pragma unroll
    for (int r = 0; r < 16; r++) {
        int row = wid * 16 + r;
        int n = n0 + row;
        float4 v = *reinterpret_cast<const float4*>(&cs[row * LDC_S + lane * 4]);
        if (!is_gat) {
            if (n < N_NODES) {
                v.x += b4.x; v.y += b4.y; v.z += b4.z; v.w += b4.w;
                *reinterpret_cast<float4*>(&g_hin[n * 128 + lane * 4]) = v;
            }
        } else {
            float s = v.x * as4.x + v.y * as4.y + v.z * as4.z + v.w * as4.w;
            float d = v.x * ad4.x + v.y * ad4.y + v.z * ad4.z + v.w * ad4.w;
#pragma unroll
            for (int o = 4; o > 0; o >>= 1) {      // reduce within 8-lane head group
                s += __shfl_xor_sync(0xffffffffu, s, o);
                d += __shfl_xor_sync(0xffffffffu, d, o);
            }
            if (n < N_NODES) {
                *reinterpret_cast<float4*>(&g_xp[n * 128 + lane * 4]) = v;
                if ((lane & 7) == 0) {
                    g_asrc[n * 4 + h] = s;
                    g_adst[n * 4 + h] = d;
                }
            }
        }
    }
}

// ---------------- K3: degree histogram ----------------
__global__ void count_kernel(const int* __restrict__ ei) {
    int i = blockIdx.x * blockDim.x + threadIdx.x;
    if (i >= M_EDGES) return;
    int d = (i < E_EDGES) ? ei[E_EDGES + i] : (i - E_EDGES);
    atomicAdd(&g_cnt[d], 1);
}

// ---------------- K4-K6: exclusive scan ----------------
__global__ void scanA_kernel() {
    __shared__ int sh[256];
    int t = threadIdx.x;
    int base = blockIdx.x * 1024 + t * 4;
    int v0 = 0, v1 = 0, v2 = 0, v3 = 0;
    if (base + 0 < N_NODES) v0 = g_cnt[base + 0];
    if (base + 1 < N_NODES) v1 = g_cnt[base + 1];
    if (base + 2 < N_NODES) v2 = g_cnt[base + 2];
    if (base + 3 < N_NODES) v3 = g_cnt[base + 3];
    int s = v0 + v1 + v2 + v3;
    sh[t] = s; __syncthreads();
    for (int off = 1; off < 256; off <<= 1) {
        int u = (t >= off) ? sh[t - off] : 0; __syncthreads();
        sh[t] += u; __syncthreads();
    }
    int run = sh[t] - s;
    if (base + 0 < N_NODES) g_rowstart[base + 0] = run; run += v0;
    if (base + 1 < N_NODES) g_rowstart[base + 1] = run; run += v1;
    if (base + 2 < N_NODES) g_rowstart[base + 2] = run; run += v2;
    if (base + 3 < N_NODES) g_rowstart[base + 3] = run;
    if (t == 255) g_blksum[blockIdx.x] = sh[255];
}

__global__ void scanB_kernel(int nb) {
    __shared__ int sh[256];
    int t = threadIdx.x;
    int v = (t < nb) ? g_blksum[t] : 0;
    sh[t] = v; __syncthreads();
    for (int off = 1; off < 256; off <<= 1) {
        int u = (t >= off) ? sh[t - off] : 0; __syncthreads();
        sh[t] += u; __syncthreads();
    }
    if (t < nb) g_blkoff[t] = sh[t] - v;
}

__global__ void scanC_kernel() {
    int t = threadIdx.x;
    int off = g_blkoff[blockIdx.x];
#pragma unroll
    for (int j = 0; j < 4; j++) {
        int i = blockIdx.x * 1024 + t * 4 + j;
        if (i < N_NODES) {
            int r = g_rowstart[i] + off;
            g_rowstart[i] = r;
            g_cursor[i] = r;
        }
    }
}

// ---------------- K7: scatter edges into CSR ----------------
__global__ void scatter_kernel(const int* __restrict__ ei) {
    int i = blockIdx.x * blockDim.x + threadIdx.x;
    if (i >= M_EDGES) return;
    int s, d;
    if (i < E_EDGES) { s = ei[i]; d = ei[E_EDGES + i]; }
    else             { s = d = i - E_EDGES; }
    int pos = atomicAdd(&g_cursor[d], 1);
    g_csr[pos] = s;
}

// ---------------- K8: one warp per dst node: softmax + aggregation (unrolled x4) ----------------
__global__ void agg_kernel(const float* __restrict__ gat_bias, float* __restrict__ out) {
    int warp = (blockIdx.x * blockDim.x + threadIdx.x) >> 5;
    int lane = threadIdx.x & 31;
    if (warp >= N_NODES) return;
    int n = warp;
    int rs = g_rowstart[n];
    int deg = g_cnt[n];
    float4 ad = reinterpret_cast<const float4*>(g_adst)[n];

    // denominator (lane-strided, all 4 heads)
    float d0 = 0.f, d1 = 0.f, d2 = 0.f, d3 = 0.f;
    for (int e = rs + lane; e < rs + deg; e += 32) {
        int s = g_csr[e];
        float4 as = reinterpret_cast<const float4*>(g_asrc)[s];
        d0 += __expf(lrelu02(as.x + ad.x));
        d1 += __expf(lrelu02(as.y + ad.y));
        d2 += __expf(lrelu02(as.z + ad.z));
        d3 += __expf(lrelu02(as.w + ad.w));
    }
#pragma unroll
    for (int o = 16; o > 0; o >>= 1) {
        d0 += __shfl_xor_sync(0xffffffffu, d0, o);
        d1 += __shfl_xor_sync(0xffffffffu, d1, o);
        d2 += __shfl_xor_sync(0xffffffffu, d2, o);
        d3 += __shfl_xor_sync(0xffffffffu, d3, o);
    }
    int h = lane >> 3;
    float ad_h  = (h == 0) ? ad.x : (h == 1) ? ad.y : (h == 2) ? ad.z : ad.w;
    float den_h = (h == 0) ? d0  : (h == 1) ? d1  : (h == 2) ? d2  : d3;
    float inv = 1.0f / den_h;

    float4 acc = make_float4(0.f, 0.f, 0.f, 0.f);
    int e = rs, end = rs + deg;
    for (; e + 4 <= end; e += 4) {
        int s0 = g_csr[e], s1 = g_csr[e + 1], s2 = g_csr[e + 2], s3 = g_csr[e + 3];
        float a0 = g_asrc[s0 * 4 + h], a1 = g_asrc[s1 * 4 + h];
        float a2 = g_asrc[s2 * 4 + h], a3 = g_asrc[s3 * 4 + h];
        float4 x0 = reinterpret_cast<const float4*>(g_xp)[s0 * 32 + lane];
        float4 x1 = reinterpret_cast<const float4*>(g_xp)[s1 * 32 + lane];
        float4 x2 = reinterpret_cast<const float4*>(g_xp)[s2 * 32 + lane];
        float4 x3 = reinterpret_cast<const float4*>(g_xp)[s3 * 32 + lane];
        float al0 = __expf(lrelu02(a0 + ad_h)) * inv;
        float al1 = __expf(lrelu02(a1 + ad_h)) * inv;
        float al2 = __expf(lrelu02(a2 + ad_h)) * inv;
        float al3 = __expf(lrelu02(a3 + ad_h)) * inv;
        acc.x += al0 * x0.x + al1 * x1.x + al2 * x2.x + al3 * x3.x;
        acc.y += al0 * x0.y + al1 * x1.y + al2 * x2.y + al3 * x3.y;
        acc.z += al0 * x0.z + al1 * x1.z + al2 * x2.z + al3 * x3.z;
        acc.w += al0 * x0.w + al1 * x1.w + al2 * x2.w + al3 * x3.w;
    }
    for (; e < end; e++) {
        int s = g_csr[e];
        float alpha = __expf(lrelu02(g_asrc[s * 4 + h] + ad_h)) * inv;
        float4 xv = reinterpret_cast<const float4*>(g_xp)[s * 32 + lane];
        acc.x += alpha * xv.x; acc.y += alpha * xv.y;
        acc.z += alpha * xv.z; acc.w += alpha * xv.w;
    }
    float4 b = reinterpret_cast<const float4*>(gat_bias)[lane];
    acc.x += b.x; acc.y += b.y; acc.z += b.z; acc.w += b.w;
    reinterpret_cast<float4*>(out)[n * 32 + lane] = acc;
}

// ---------------- K9: column statistics for BatchNorm ----------------
__global__ void colstats_kernel(const float* __restrict__ y) {
    int t = threadIdx.x;
    float s = 0.f, ss = 0.f;
    for (int r = blockIdx.x; r < N_NODES; r += gridDim.x) {
        float v = y[r * 128 + t];
        s += v; ss += v * v;
    }
    atomicAdd(&g_colsum[t], s);
    atomicAdd(&g_colsumsq[t], ss);
}

// ---------------- K10: BN + ELU + residual ----------------
__global__ void final_kernel(float* __restrict__ out,
                             const float* __restrict__ gamma, const float* __restrict__ beta) {
    int i = blockIdx.x * blockDim.x + threadIdx.x;
    if (i >= N_NODES * 128) return;
    int c = i & 127;
    const float invN = 1.0f / (float)N_NODES;
    float mu = g_colsum[c] * invN;
    float var = g_colsumsq[c] * invN - mu * mu;
    float y = out[i];
    float t = (y - mu) * rsqrtf(var + 1e-5f) * gamma[c] + beta[c];
    float h = t > 0.f ? t : expm1f(t);
    out[i] = g_hin[i] + h;
}

// ---------------- launch ----------------
extern "C" void kernel_launch(void* const* d_in, const int* in_sizes, int n_in,
                              void* d_out, int out_size) {
    const float* x        = (const float*)d_in[0];
    const int*   ei       = (const int*)  d_in[1];
    const float* lin_w    = (const float*)d_in[2];
    const float* lin_b    = (const float*)d_in[3];
    const float* gat_w    = (const float*)d_in[4];
    const float* att_src  = (const float*)d_in[5];
    const float* att_dst  = (const float*)d_in[6];
    const float* gat_bias = (const float*)d_in[7];
    const float* bn_gamma = (const float*)d_in[8];
    const float* bn_beta  = (const float*)d_in[9];
    float* out = (float*)d_out;

    cudaFuncSetAttribute(gemm_kernel, cudaFuncAttributeMaxDynamicSharedMemorySize, GEMM_SMEM);

    const int NB = (N_NODES + 1023) / 1024;

    init_kernel<<<(N_NODES + 255) / 256, 256>>>();
    gemm_kernel<<<dim3((N_NODES + 127) / 128, 2), 256, GEMM_SMEM>>>(
        x, lin_w, lin_b, gat_w, att_src, att_dst);
    count_kernel<<<(M_EDGES + 255) / 256, 256>>>(ei);
    scanA_kernel<<<NB, 256>>>();
    scanB_kernel<<<1, 256>>>(NB);
    scanC_kernel<<<NB, 256>>>();
    scatter_kernel<<<(M_EDGES + 255) / 256, 256>>>(ei);
    agg_kernel<<<(N_NODES + 7) / 8, 256>>>(gat_bias, out);
    colstats_kernel<<<512, 128>>>(out);
    final_kernel<<<(N_NODES * 128 + 255) / 256, 256>>>(out, bn_gamma, bn_beta);
}